// round 1
// baseline (speedup 1.0000x reference)
#include <cuda_runtime.h>
#include <math.h>

// Problem constants (fixed by the reference setup_inputs)
#define NPTS 100000
#define KNBR 9
#define CDIM 256
#define BM   64
#define KDEPTH (KNBR * CDIM)        // 2304
#define KT_STEPS (KDEPTH / 8)       // 288

// ---- scratch (device globals: allocation-free) ----
__device__ int   g_mask_u8;                         // 1 if mask is 1-byte elements
__device__ int   g_nbr[NPTS * KNBR];                // masked neighbor idx, -1 = off
__device__ float g_mid[(size_t)NPTS * CDIM];        // conv1->LN->gelu output

// ---------------------------------------------------------------------------
// Kernel 1: detect mask element width.
// If mask is float32: words are {0x00000000, 0x3F800000}.
// If int32:          words are {0, 1}.
// If uint8/bool:     words are 4 packed 0/1 bytes (e.g. 0x01000101) -> values
//                    outside {0,1,0x3F800000} appear with overwhelming prob
//                    in the first 1024 words (p ~ 1 - 0.027^1024).
// ---------------------------------------------------------------------------
__global__ void detect_mask_kernel(const unsigned int* __restrict__ m) {
    __shared__ int flag;
    if (threadIdx.x == 0) flag = 0;
    __syncthreads();
    for (int i = threadIdx.x; i < 1024; i += blockDim.x) {
        unsigned w = m[i];
        if (w != 0u && w != 1u && w != 0x3F800000u) flag = 1;
    }
    __syncthreads();
    if (threadIdx.x == 0) g_mask_u8 = flag;
}

// ---------------------------------------------------------------------------
// Kernel 2: fold mask into neighbor index table (-1 = masked out).
// Truthiness (word != 0) is correct for both int32 {0,1} and float32
// {0.0f, 1.0f} interpretations, so only width matters.
// ---------------------------------------------------------------------------
__global__ void build_nbr_kernel(const int* __restrict__ idx,
                                 const void* __restrict__ mask) {
    int i = blockIdx.x * blockDim.x + threadIdx.x;
    if (i >= NPTS * KNBR) return;
    bool on;
    if (g_mask_u8)
        on = ((const unsigned char*)mask)[i] != 0;
    else
        on = ((const unsigned int*)mask)[i] != 0u;
    g_nbr[i] = on ? idx[i] : -1;
}

__device__ __forceinline__ float gelu_exact(float x) {
    return 0.5f * x * (1.0f + erff(x * 0.70710678118654752f));
}

// ---------------------------------------------------------------------------
// Kernel 3/4: fused gathered-GEMM + LayerNorm (+residual) + GELU.
//   dst[m, :] = epilogue( sum_k mask(m,k) * src[nbr(m,k), :] @ W[k] )
// Tile: 64 rows x 256 cols per CTA, depth-8 k-steps, double-buffered smem.
// 256 threads: warp w owns rows w*8..w*8+7, lane owns cols lane*8..lane*8+7.
// A smem padded to 68 floats/row -> conflict-free STS; A reads are warp
// broadcasts; B tile is a contiguous 8KB slab of W (fully coalesced).
// ---------------------------------------------------------------------------
template <bool HAS_RES>
__global__ __launch_bounds__(256, 2)
void fused_conv_ln_gelu(const float* __restrict__ src,
                        const float* __restrict__ Wt,     // [9][256][256]
                        const float* __restrict__ gamma,
                        const float* __restrict__ beta,
                        const float* __restrict__ resid,  // may be null
                        float* __restrict__ dst) {
    __shared__ int   nbr_s[BM * KNBR];
    __shared__ float As[2][8][68];     // [buf][kk][m(+pad)]
    __shared__ float Bs[2][8][256];    // [buf][kk][n]

    const int tid  = threadIdx.x;
    const int lane = tid & 31;
    const int warp = tid >> 5;
    const int m0   = blockIdx.x * BM;

    // neighbor table for this block's rows (guard tail block)
    for (int i = tid; i < BM * KNBR; i += 256) {
        int m = m0 + i / KNBR;
        nbr_s[i] = (m < NPTS) ? g_nbr[m * KNBR + (i % KNBR)] : -1;
    }
    __syncthreads();

    // per-thread load coordinates (A: 2 scalars, B: 2 float4)
    const int ma0 = tid >> 3;          // 0..31
    const int ma1 = ma0 + 32;          // 32..63
    const int ja  = tid & 7;

    // ---- prologue: load tile 0 into registers ----
    float  an0, an1;
    float4 bn0, bn1;
    {
        const int kkA = 0, cb = 0;
        int r0 = nbr_s[ma0 * KNBR + kkA];
        int r1 = nbr_s[ma1 * KNBR + kkA];
        an0 = (r0 >= 0) ? __ldg(src + (size_t)r0 * CDIM + cb + ja) : 0.0f;
        an1 = (r1 >= 0) ? __ldg(src + (size_t)r1 * CDIM + cb + ja) : 0.0f;
        const float4* Wb = (const float4*)(Wt);
        bn0 = Wb[tid];
        bn1 = Wb[tid + 256];
    }

    float acc[8][8];
#pragma unroll
    for (int r = 0; r < 8; r++)
#pragma unroll
        for (int s = 0; s < 8; s++) acc[r][s] = 0.0f;

    for (int kt = 0; kt < KT_STEPS; ++kt) {
        const int cur = kt & 1;

        // stage tile kt (currently in regs) to smem buffer `cur`
        As[cur][ja][ma0] = an0;
        As[cur][ja][ma1] = an1;
        {
            float4* Bsv = (float4*)&Bs[cur][0][0];
            Bsv[tid]       = bn0;
            Bsv[tid + 256] = bn1;
        }
        __syncthreads();

        // issue global loads for tile kt+1 (overlap with compute)
        if (kt + 1 < KT_STEPS) {
            const int ktn = kt + 1;
            const int kkA = ktn >> 5;          // neighbor slot 0..8
            const int cb  = (ktn & 31) << 3;   // input-channel base
            int r0 = nbr_s[ma0 * KNBR + kkA];
            int r1 = nbr_s[ma1 * KNBR + kkA];
            an0 = (r0 >= 0) ? __ldg(src + (size_t)r0 * CDIM + cb + ja) : 0.0f;
            an1 = (r1 >= 0) ? __ldg(src + (size_t)r1 * CDIM + cb + ja) : 0.0f;
            const float4* Wb =
                (const float4*)(Wt + (size_t)kkA * (CDIM * CDIM) + (size_t)cb * CDIM);
            bn0 = Wb[tid];
            bn1 = Wb[tid + 256];
        }

        // compute 64x256 += A[64x8] * B[8x256] microtiled 8x8
#pragma unroll
        for (int kk = 0; kk < 8; kk++) {
            const float4 a0v = *(const float4*)&As[cur][kk][warp * 8];
            const float4 a1v = *(const float4*)&As[cur][kk][warp * 8 + 4];
            const float4 b0v = *(const float4*)&Bs[cur][kk][lane * 8];
            const float4 b1v = *(const float4*)&Bs[cur][kk][lane * 8 + 4];
            float aa[8] = {a0v.x, a0v.y, a0v.z, a0v.w, a1v.x, a1v.y, a1v.z, a1v.w};
            float bb[8] = {b0v.x, b0v.y, b0v.z, b0v.w, b1v.x, b1v.y, b1v.z, b1v.w};
#pragma unroll
            for (int r = 0; r < 8; r++)
#pragma unroll
                for (int s = 0; s < 8; s++)
                    acc[r][s] = fmaf(aa[r], bb[s], acc[r][s]);
        }
        __syncthreads();
    }

    // ---- epilogue: LayerNorm per row (warp owns full 256-wide rows) ----
    float gam[8], bet[8];
#pragma unroll
    for (int s = 0; s < 8; s++) {
        gam[s] = __ldg(&gamma[lane * 8 + s]);
        bet[s] = __ldg(&beta[lane * 8 + s]);
    }

#pragma unroll
    for (int r = 0; r < 8; r++) {
        float s1 = 0.0f, s2 = 0.0f;
#pragma unroll
        for (int s = 0; s < 8; s++) {
            s1 += acc[r][s];
            s2 += acc[r][s] * acc[r][s];
        }
#pragma unroll
        for (int o = 16; o > 0; o >>= 1) {
            s1 += __shfl_xor_sync(0xFFFFFFFFu, s1, o);
            s2 += __shfl_xor_sync(0xFFFFFFFFu, s2, o);
        }
        const float mu  = s1 * (1.0f / 256.0f);
        const float var = s2 * (1.0f / 256.0f) - mu * mu;
        const float inv = rsqrtf(var + 1e-6f);

        const int mg = m0 + warp * 8 + r;
        if (mg < NPTS) {
            float v[8];
#pragma unroll
            for (int s = 0; s < 8; s++)
                v[s] = (acc[r][s] - mu) * inv * gam[s] + bet[s];
            if (HAS_RES) {
                const float4 r0 = __ldg((const float4*)(resid + (size_t)mg * CDIM + lane * 8));
                const float4 r1 = __ldg((const float4*)(resid + (size_t)mg * CDIM + lane * 8 + 4));
                v[0] += r0.x; v[1] += r0.y; v[2] += r0.z; v[3] += r0.w;
                v[4] += r1.x; v[5] += r1.y; v[6] += r1.z; v[7] += r1.w;
            }
#pragma unroll
            for (int s = 0; s < 8; s++) v[s] = gelu_exact(v[s]);
            float4* o = (float4*)(dst + (size_t)mg * CDIM + lane * 8);
            o[0] = make_float4(v[0], v[1], v[2], v[3]);
            o[1] = make_float4(v[4], v[5], v[6], v[7]);
        }
    }
}

// ---------------------------------------------------------------------------
// Launch: 4 kernels on the capture stream. Inputs (metadata order):
//   0 feats[N,C] f32, 1 W1[K,C,C] f32, 2 gamma1[C], 3 beta1[C],
//   4 W2[K,C,C], 5 gamma2[C], 6 beta2[C], 7 neighbor_idx[N,K] i32,
//   8 neighbor_mask[N,K] (bool -> u8/i32/f32, auto-detected)
// ---------------------------------------------------------------------------
extern "C" void kernel_launch(void* const* d_in, const int* in_sizes, int n_in,
                              void* d_out, int out_size) {
    const float* feats  = (const float*)d_in[0];
    const float* W1     = (const float*)d_in[1];
    const float* gamma1 = (const float*)d_in[2];
    const float* beta1  = (const float*)d_in[3];
    const float* W2     = (const float*)d_in[4];
    const float* gamma2 = (const float*)d_in[5];
    const float* beta2  = (const float*)d_in[6];
    const int*   nbr    = (const int*)d_in[7];
    const void*  mask   = (const void*)d_in[8];
    float*       out    = (float*)d_out;

    float* mid;
    cudaGetSymbolAddress((void**)&mid, g_mid);

    detect_mask_kernel<<<1, 256>>>((const unsigned int*)mask);

    const int nm = NPTS * KNBR;
    build_nbr_kernel<<<(nm + 255) / 256, 256>>>(nbr, mask);

    const int grid = (NPTS + BM - 1) / BM;  // 1563
    fused_conv_ln_gelu<false><<<grid, 256>>>(feats, W1, gamma1, beta1, nullptr, mid);
    fused_conv_ln_gelu<true><<<grid, 256>>>(mid,   W2, gamma2, beta2, feats,   out);
}

// round 3
// speedup vs baseline: 2.5170x; 2.5170x over previous
#include <cuda_runtime.h>
#include <cstdint>
#include <math.h>

// ---------------- problem constants ----------------
#define NPTS 100000
#define KNBR 9
#define CDIM 256
#define BM   128                  // rows per CTA
#define THREADS 512               // 16 warps: 4 (M) x 4 (N)
#define KSTEP 32                  // channels per k-chunk
#define NKT  72                   // 9 neighbors * 256/32

// ---------------- scratch ----------------
__device__ int   g_mask_u8;
__device__ int   g_nbr[NPTS * KNBR];
__device__ float g_mid[(size_t)NPTS * CDIM];

// ---------------- smem layout (host-visible for sizeof) ----------------
struct Smem {
    float As[2][BM][36];      // [buf][m][k+pad4]   36864 B
    float Bs[2][KSTEP][264];  // [buf][k][n+pad8]   67584 B
    int   nbr[BM * KNBR];     //                     4608 B
    float gam[CDIM], bet[CDIM];
    float red1[BM][4], red2[BM][4];
    float mu[BM], inv[BM];
};

// ---------------- helpers ----------------
__device__ __forceinline__ uint32_t f2tf(float x) {
    uint32_t u;
    asm("cvt.rna.tf32.f32 %0, %1;" : "=r"(u) : "f"(x));
    return u;
}
__device__ __forceinline__ float4 cvt4(float4 v) {
    v.x = __uint_as_float(f2tf(v.x));
    v.y = __uint_as_float(f2tf(v.y));
    v.z = __uint_as_float(f2tf(v.z));
    v.w = __uint_as_float(f2tf(v.w));
    return v;
}
__device__ __forceinline__ void mma8(float* c, const uint32_t* a, uint32_t b0, uint32_t b1) {
    asm volatile(
        "mma.sync.aligned.m16n8k8.row.col.f32.tf32.tf32.f32 "
        "{%0,%1,%2,%3}, {%4,%5,%6,%7}, {%8,%9}, {%0,%1,%2,%3};"
        : "+f"(c[0]), "+f"(c[1]), "+f"(c[2]), "+f"(c[3])
        : "r"(a[0]), "r"(a[1]), "r"(a[2]), "r"(a[3]), "r"(b0), "r"(b1));
}
__device__ __forceinline__ float gelu_exact(float x) {
    return 0.5f * x * (1.0f + erff(x * 0.70710678118654752f));
}

// ---------------- small kernels ----------------
__global__ void detect_mask_kernel(const unsigned int* __restrict__ m) {
    __shared__ int flag;
    if (threadIdx.x == 0) flag = 0;
    __syncthreads();
    for (int i = threadIdx.x; i < 1024; i += blockDim.x) {
        unsigned w = m[i];
        if (w != 0u && w != 1u && w != 0x3F800000u) flag = 1;
    }
    __syncthreads();
    if (threadIdx.x == 0) g_mask_u8 = flag;
}

__global__ void build_nbr_kernel(const int* __restrict__ idx, const void* __restrict__ mask) {
    int i = blockIdx.x * blockDim.x + threadIdx.x;
    if (i >= NPTS * KNBR) return;
    bool on = g_mask_u8 ? (((const unsigned char*)mask)[i] != 0)
                        : (((const unsigned int*)mask)[i] != 0u);
    g_nbr[i] = on ? idx[i] : -1;
}

// ---------------- fused mma.sync conv + LN + GELU (+res) ----------------
template <bool HAS_RES>
__global__ __launch_bounds__(THREADS, 1)
void conv_mma(const float* __restrict__ src, const float* __restrict__ W,
              const float* __restrict__ gamma, const float* __restrict__ beta,
              const float* __restrict__ resid, float* __restrict__ dst) {
    extern __shared__ unsigned char sm_raw[];
    Smem* sm = (Smem*)sm_raw;

    const int tid  = threadIdx.x;
    const int lane = tid & 31;
    const int wid  = tid >> 5;
    const int wm   = wid & 3;   // M warp coord (rows wm*32..+32)
    const int wn   = wid >> 2;  // N warp coord (cols wn*64..+64)
    const int m0   = blockIdx.x * BM;

    // ---- fill nbr / gamma / beta ----
    for (int i = tid; i < BM * KNBR; i += THREADS) {
        int m = m0 + i / KNBR;
        sm->nbr[i] = (m < NPTS) ? g_nbr[(size_t)m * KNBR + (i % KNBR)] : -1;
    }
    if (tid < CDIM) { sm->gam[tid] = gamma[tid]; sm->bet[tid] = beta[tid]; }
    __syncthreads();

    // ---- per-thread load coordinates (loop-invariant) ----
    const int rowA = tid >> 2;       // 0..127
    const int jA   = tid & 3;        // float4 slot (and slot+4)
    int kBq[4], n4q[4];
#pragma unroll
    for (int q = 0; q < 4; q++) {
        int idx = q * THREADS + tid;
        kBq[q] = idx >> 6;           // 0..31
        n4q[q] = idx & 63;           // float4 col
    }

    // ---- prologue: load chunk 0 into registers ----
    float4 rA0, rA1, rB[4];
    {
        const int kk = 0, cb = 0;
        int r = sm->nbr[rowA * KNBR + kk];
        if (r >= 0) {
            const float4* ap = (const float4*)(src + ((size_t)r << 8) + cb);
            rA0 = cvt4(__ldg(ap + jA));
            rA1 = cvt4(__ldg(ap + jA + 4));
        } else {
            rA0 = make_float4(0.f, 0.f, 0.f, 0.f);
            rA1 = rA0;
        }
#pragma unroll
        for (int q = 0; q < 4; q++)
            rB[q] = cvt4(__ldg((const float4*)(W + (size_t)(cb + kBq[q]) * CDIM) + n4q[q]));
    }

    float acc[2][8][4];
#pragma unroll
    for (int mt = 0; mt < 2; mt++)
#pragma unroll
        for (int nt = 0; nt < 8; nt++)
#pragma unroll
            for (int e = 0; e < 4; e++) acc[mt][nt][e] = 0.0f;

    const int rb = (wm << 5) + (lane >> 2);  // row base in CTA tile
    const int cl = lane & 3;

    // ---- main loop over 72 k-chunks ----
    for (int kt = 0; kt < NKT; ++kt) {
        const int cur = kt & 1;

        // stage regs -> smem
        *(float4*)&sm->As[cur][rowA][jA * 4]      = rA0;
        *(float4*)&sm->As[cur][rowA][jA * 4 + 16] = rA1;
#pragma unroll
        for (int q = 0; q < 4; q++)
            *(float4*)&sm->Bs[cur][kBq[q]][n4q[q] * 4] = rB[q];
        __syncthreads();

        // prefetch next chunk
        if (kt + 1 < NKT) {
            const int ktn = kt + 1;
            const int kk = ktn >> 3;
            const int cb = (ktn & 7) << 5;
            int r = sm->nbr[rowA * KNBR + kk];
            if (r >= 0) {
                const float4* ap = (const float4*)(src + ((size_t)r << 8) + cb);
                rA0 = cvt4(__ldg(ap + jA));
                rA1 = cvt4(__ldg(ap + jA + 4));
            } else {
                rA0 = make_float4(0.f, 0.f, 0.f, 0.f);
                rA1 = rA0;
            }
            const float* Wk = W + ((size_t)kk << 16) + (size_t)cb * CDIM;
#pragma unroll
            for (int q = 0; q < 4; q++)
                rB[q] = cvt4(__ldg((const float4*)(Wk + (size_t)kBq[q] * CDIM) + n4q[q]));
        }

        // compute: 4 sub-steps of k=8
#pragma unroll
        for (int ks = 0; ks < 4; ks++) {
            uint32_t af[2][4];
#pragma unroll
            for (int mt = 0; mt < 2; mt++) {
                int r = rb + mt * 16;
                af[mt][0] = __float_as_uint(sm->As[cur][r][ks * 8 + cl]);
                af[mt][1] = __float_as_uint(sm->As[cur][r + 8][ks * 8 + cl]);
                af[mt][2] = __float_as_uint(sm->As[cur][r][ks * 8 + cl + 4]);
                af[mt][3] = __float_as_uint(sm->As[cur][r + 8][ks * 8 + cl + 4]);
            }
#pragma unroll
            for (int nt = 0; nt < 8; nt++) {
                int n = (wn << 6) + nt * 8 + (lane >> 2);
                uint32_t b0 = __float_as_uint(sm->Bs[cur][ks * 8 + cl][n]);
                uint32_t b1 = __float_as_uint(sm->Bs[cur][ks * 8 + cl + 4][n]);
                mma8(acc[0][nt], af[0], b0, b1);
                mma8(acc[1][nt], af[1], b0, b1);
            }
        }
        __syncthreads();
    }

    // ---- LayerNorm reduction ----
#pragma unroll
    for (int mt = 0; mt < 2; mt++) {
        float s1a = 0.f, s2a = 0.f, s1b = 0.f, s2b = 0.f;
#pragma unroll
        for (int nt = 0; nt < 8; nt++) {
            float v0 = acc[mt][nt][0], v1 = acc[mt][nt][1];
            float v2 = acc[mt][nt][2], v3 = acc[mt][nt][3];
            s1a += v0 + v1; s2a += v0 * v0 + v1 * v1;
            s1b += v2 + v3; s2b += v2 * v2 + v3 * v3;
        }
#pragma unroll
        for (int o = 1; o < 4; o <<= 1) {
            s1a += __shfl_xor_sync(0xFFFFFFFFu, s1a, o);
            s2a += __shfl_xor_sync(0xFFFFFFFFu, s2a, o);
            s1b += __shfl_xor_sync(0xFFFFFFFFu, s1b, o);
            s2b += __shfl_xor_sync(0xFFFFFFFFu, s2b, o);
        }
        if ((lane & 3) == 0) {
            int r = (wm << 5) + (mt << 4) + (lane >> 2);
            sm->red1[r][wn] = s1a; sm->red2[r][wn] = s2a;
            sm->red1[r + 8][wn] = s1b; sm->red2[r + 8][wn] = s2b;
        }
    }
    __syncthreads();
    if (tid < BM) {
        float s1 = sm->red1[tid][0] + sm->red1[tid][1] + sm->red1[tid][2] + sm->red1[tid][3];
        float s2 = sm->red2[tid][0] + sm->red2[tid][1] + sm->red2[tid][2] + sm->red2[tid][3];
        float mu  = s1 * (1.0f / 256.0f);
        float var = s2 * (1.0f / 256.0f) - mu * mu;
        sm->mu[tid]  = mu;
        sm->inv[tid] = rsqrtf(var + 1e-6f);
    }
    __syncthreads();

    // ---- normalize + residual + GELU + store ----
#pragma unroll
    for (int mt = 0; mt < 2; mt++) {
#pragma unroll
        for (int hf = 0; hf < 2; hf++) {
            int r = (wm << 5) + (mt << 4) + (lane >> 2) + hf * 8;
            int m = m0 + r;
            if (m < NPTS) {
                float mu = sm->mu[r], inv = sm->inv[r];
#pragma unroll
                for (int nt = 0; nt < 8; nt++) {
                    int n = (wn << 6) + nt * 8 + ((lane & 3) << 1);
                    float v0 = acc[mt][nt][hf * 2 + 0];
                    float v1 = acc[mt][nt][hf * 2 + 1];
                    v0 = (v0 - mu) * inv * sm->gam[n]     + sm->bet[n];
                    v1 = (v1 - mu) * inv * sm->gam[n + 1] + sm->bet[n + 1];
                    if (HAS_RES) {
                        float2 rr = *(const float2*)(resid + (size_t)m * CDIM + n);
                        v0 += rr.x; v1 += rr.y;
                    }
                    v0 = gelu_exact(v0);
                    v1 = gelu_exact(v1);
                    *(float2*)(dst + (size_t)m * CDIM + n) = make_float2(v0, v1);
                }
            }
        }
    }
}

// ---------------- launch ----------------
extern "C" void kernel_launch(void* const* d_in, const int* in_sizes, int n_in,
                              void* d_out, int out_size) {
    const float* feats  = (const float*)d_in[0];
    const float* W1     = (const float*)d_in[1];
    const float* gamma1 = (const float*)d_in[2];
    const float* beta1  = (const float*)d_in[3];
    const float* W2     = (const float*)d_in[4];
    const float* gamma2 = (const float*)d_in[5];
    const float* beta2  = (const float*)d_in[6];
    const int*   nbr    = (const int*)d_in[7];
    const void*  mask   = (const void*)d_in[8];
    float*       out    = (float*)d_out;

    float* mid;
    cudaGetSymbolAddress((void**)&mid, g_mid);

    const int smem_bytes = (int)sizeof(Smem);
    cudaFuncSetAttribute(conv_mma<false>, cudaFuncAttributeMaxDynamicSharedMemorySize, smem_bytes);
    cudaFuncSetAttribute(conv_mma<true>,  cudaFuncAttributeMaxDynamicSharedMemorySize, smem_bytes);

    detect_mask_kernel<<<1, 256>>>((const unsigned int*)mask);
    build_nbr_kernel<<<(NPTS * KNBR + 255) / 256, 256>>>(nbr, mask);

    const int grid = (NPTS + BM - 1) / BM;  // 782
    conv_mma<false><<<grid, THREADS, smem_bytes>>>(feats, W1, gamma1, beta1, nullptr, mid);
    conv_mma<true><<<grid, THREADS, smem_bytes>>>(mid,  W2, gamma2, beta2, feats,   out);
}

// round 4
// speedup vs baseline: 3.5575x; 1.4134x over previous
#include <cuda_runtime.h>
#include <cstdint>
#include <math.h>

// ---------------- problem constants ----------------
#define NPTS 100000
#define KNBR 9
#define CDIM 256
#define BM   128                  // rows per CTA
#define THREADS 512               // 16 warps: 4 (M) x 4 (N)
#define KSTEP 32                  // channels per k-chunk
#define NKT  72                   // 9 neighbors * 256/32
#define NSTG 4                    // cp.async pipeline depth

// ---------------- scratch ----------------
__device__ int   g_mask_u8;
__device__ int   g_nbr[NPTS * KNBR];
__device__ float g_mid[(size_t)NPTS * CDIM];

// ---------------- smem layout ----------------
struct Smem {
    float As[NSTG][BM][36];       // [stage][m][k+pad]    73728 B
    float Bs[NSTG][KSTEP][264];   // [stage][k][n+pad]   135168 B
    int   nbr[BM * KNBR];
    float gam[CDIM], bet[CDIM];
    float red1[BM][4], red2[BM][4];
    float mu[BM], inv[BM];
};                                 // ~220.7 KB total

// ---------------- helpers ----------------
__device__ __forceinline__ void cp16(uint32_t dst, const void* src, uint32_t sz) {
    asm volatile("cp.async.cg.shared.global [%0], [%1], 16, %2;"
                 :: "r"(dst), "l"(src), "r"(sz) : "memory");
}
#define CP_COMMIT() asm volatile("cp.async.commit_group;" ::: "memory")
#define CP_WAIT2()  asm volatile("cp.async.wait_group 2;" ::: "memory")

__device__ __forceinline__ void mma8(float* c, const uint32_t* a, uint32_t b0, uint32_t b1) {
    asm volatile(
        "mma.sync.aligned.m16n8k8.row.col.f32.tf32.tf32.f32 "
        "{%0,%1,%2,%3}, {%4,%5,%6,%7}, {%8,%9}, {%0,%1,%2,%3};"
        : "+f"(c[0]), "+f"(c[1]), "+f"(c[2]), "+f"(c[3])
        : "r"(a[0]), "r"(a[1]), "r"(a[2]), "r"(a[3]), "r"(b0), "r"(b1));
}
__device__ __forceinline__ float gelu_exact(float x) {
    return 0.5f * x * (1.0f + erff(x * 0.70710678118654752f));
}

// ---------------- small kernels ----------------
__global__ void detect_mask_kernel(const unsigned int* __restrict__ m) {
    __shared__ int flag;
    if (threadIdx.x == 0) flag = 0;
    __syncthreads();
    for (int i = threadIdx.x; i < 1024; i += blockDim.x) {
        unsigned w = m[i];
        if (w != 0u && w != 1u && w != 0x3F800000u) flag = 1;
    }
    __syncthreads();
    if (threadIdx.x == 0) g_mask_u8 = flag;
}

__global__ void build_nbr_kernel(const int* __restrict__ idx, const void* __restrict__ mask) {
    int i = blockIdx.x * blockDim.x + threadIdx.x;
    if (i >= NPTS * KNBR) return;
    bool on = g_mask_u8 ? (((const unsigned char*)mask)[i] != 0)
                        : (((const unsigned int*)mask)[i] != 0u);
    g_nbr[i] = on ? idx[i] : -1;
}

// ---------------- stage loader (cp.async) ----------------
__device__ __forceinline__ void issue_stage(Smem* sm, int st, int kt,
                                            const float* __restrict__ src,
                                            const float* __restrict__ W, int tid) {
    const int kk = kt >> 3;            // neighbor slot
    const int cb = (kt & 7) << 5;      // channel base
    // A gather: 128 rows x 32 floats (2 x 16B per thread), zero-fill if masked
    {
        const int row = tid >> 2, j = tid & 3;
        const int r = sm->nbr[row * KNBR + kk];
        const uint32_t sz = (r >= 0) ? 16u : 0u;
        const float* gp = src + ((size_t)(r >= 0 ? r : 0) << 8) + cb;
        cp16((uint32_t)__cvta_generic_to_shared(&sm->As[st][row][j * 4]),      gp + j * 4,      sz);
        cp16((uint32_t)__cvta_generic_to_shared(&sm->As[st][row][j * 4 + 16]), gp + j * 4 + 16, sz);
    }
    // B: 32 k-rows x 256 floats (4 x 16B per thread)
    {
        const int k = tid >> 4;
        const int s0 = tid & 15;
        const float* wp = W + ((size_t)kk << 16) + ((size_t)(cb + k) << 8);
#pragma unroll
        for (int q = 0; q < 4; q++) {
            const int n4 = s0 + q * 16;
            cp16((uint32_t)__cvta_generic_to_shared(&sm->Bs[st][k][n4 * 4]), wp + n4 * 4, 16u);
        }
    }
}

// ---------------- fused mma.sync conv + LN + GELU (+res) ----------------
template <bool HAS_RES>
__global__ __launch_bounds__(THREADS, 1)
void conv_mma(const float* __restrict__ src, const float* __restrict__ W,
              const float* __restrict__ gamma, const float* __restrict__ beta,
              const float* __restrict__ resid, float* __restrict__ dst) {
    extern __shared__ unsigned char sm_raw[];
    Smem* sm = (Smem*)sm_raw;

    const int tid  = threadIdx.x;
    const int lane = tid & 31;
    const int wid  = tid >> 5;
    const int wm   = wid & 3;   // M warp coord
    const int wn   = wid >> 2;  // N warp coord
    const int m0   = blockIdx.x * BM;

    for (int i = tid; i < BM * KNBR; i += THREADS) {
        int m = m0 + i / KNBR;
        sm->nbr[i] = (m < NPTS) ? g_nbr[(size_t)m * KNBR + (i % KNBR)] : -1;
    }
    if (tid < CDIM) { sm->gam[tid] = gamma[tid]; sm->bet[tid] = beta[tid]; }
    __syncthreads();

    // prologue: fill stages 0..2
#pragma unroll
    for (int s = 0; s < NSTG - 1; s++) {
        issue_stage(sm, s, s, src, W, tid);
        CP_COMMIT();
    }

    float acc[2][8][4];
#pragma unroll
    for (int mt = 0; mt < 2; mt++)
#pragma unroll
        for (int nt = 0; nt < 8; nt++)
#pragma unroll
            for (int e = 0; e < 4; e++) acc[mt][nt][e] = 0.0f;

    const int rb = (wm << 5) + (lane >> 2);
    const int cl = lane & 3;

    for (int kt = 0; kt < NKT; ++kt) {
        CP_WAIT2();
        __syncthreads();

        if (kt + NSTG - 1 < NKT)
            issue_stage(sm, (kt + NSTG - 1) & (NSTG - 1), kt + NSTG - 1, src, W, tid);
        CP_COMMIT();   // empty groups at tail keep the wait_group count aligned

        const int cur = kt & (NSTG - 1);
#pragma unroll
        for (int ks = 0; ks < 4; ks++) {
            uint32_t af[2][4];
#pragma unroll
            for (int mt = 0; mt < 2; mt++) {
                int r = rb + mt * 16;
                af[mt][0] = __float_as_uint(sm->As[cur][r][ks * 8 + cl]);
                af[mt][1] = __float_as_uint(sm->As[cur][r + 8][ks * 8 + cl]);
                af[mt][2] = __float_as_uint(sm->As[cur][r][ks * 8 + cl + 4]);
                af[mt][3] = __float_as_uint(sm->As[cur][r + 8][ks * 8 + cl + 4]);
            }
#pragma unroll
            for (int nt = 0; nt < 8; nt++) {
                int n = (wn << 6) + nt * 8 + (lane >> 2);
                uint32_t b0 = __float_as_uint(sm->Bs[cur][ks * 8 + cl][n]);
                uint32_t b1 = __float_as_uint(sm->Bs[cur][ks * 8 + cl + 4][n]);
                mma8(acc[0][nt], af[0], b0, b1);
                mma8(acc[1][nt], af[1], b0, b1);
            }
        }
    }

    // ---- LayerNorm reduction ----
    __syncthreads();
#pragma unroll
    for (int mt = 0; mt < 2; mt++) {
        float s1a = 0.f, s2a = 0.f, s1b = 0.f, s2b = 0.f;
#pragma unroll
        for (int nt = 0; nt < 8; nt++) {
            float v0 = acc[mt][nt][0], v1 = acc[mt][nt][1];
            float v2 = acc[mt][nt][2], v3 = acc[mt][nt][3];
            s1a += v0 + v1; s2a += v0 * v0 + v1 * v1;
            s1b += v2 + v3; s2b += v2 * v2 + v3 * v3;
        }
#pragma unroll
        for (int o = 1; o < 4; o <<= 1) {
            s1a += __shfl_xor_sync(0xFFFFFFFFu, s1a, o);
            s2a += __shfl_xor_sync(0xFFFFFFFFu, s2a, o);
            s1b += __shfl_xor_sync(0xFFFFFFFFu, s1b, o);
            s2b += __shfl_xor_sync(0xFFFFFFFFu, s2b, o);
        }
        if ((lane & 3) == 0) {
            int r = (wm << 5) + (mt << 4) + (lane >> 2);
            sm->red1[r][wn] = s1a; sm->red2[r][wn] = s2a;
            sm->red1[r + 8][wn] = s1b; sm->red2[r + 8][wn] = s2b;
        }
    }
    __syncthreads();
    if (tid < BM) {
        float s1 = sm->red1[tid][0] + sm->red1[tid][1] + sm->red1[tid][2] + sm->red1[tid][3];
        float s2 = sm->red2[tid][0] + sm->red2[tid][1] + sm->red2[tid][2] + sm->red2[tid][3];
        float mu  = s1 * (1.0f / 256.0f);
        float var = s2 * (1.0f / 256.0f) - mu * mu;
        sm->mu[tid]  = mu;
        sm->inv[tid] = rsqrtf(var + 1e-6f);
    }
    __syncthreads();

    // ---- normalize + residual + GELU + store ----
#pragma unroll
    for (int mt = 0; mt < 2; mt++) {
#pragma unroll
        for (int hf = 0; hf < 2; hf++) {
            int r = (wm << 5) + (mt << 4) + (lane >> 2) + hf * 8;
            int m = m0 + r;
            if (m < NPTS) {
                float mu = sm->mu[r], inv = sm->inv[r];
#pragma unroll
                for (int nt = 0; nt < 8; nt++) {
                    int n = (wn << 6) + nt * 8 + ((lane & 3) << 1);
                    float v0 = acc[mt][nt][hf * 2 + 0];
                    float v1 = acc[mt][nt][hf * 2 + 1];
                    v0 = (v0 - mu) * inv * sm->gam[n]     + sm->bet[n];
                    v1 = (v1 - mu) * inv * sm->gam[n + 1] + sm->bet[n + 1];
                    if (HAS_RES) {
                        float2 rr = *(const float2*)(resid + (size_t)m * CDIM + n);
                        v0 += rr.x; v1 += rr.y;
                    }
                    v0 = gelu_exact(v0);
                    v1 = gelu_exact(v1);
                    *(float2*)(dst + (size_t)m * CDIM + n) = make_float2(v0, v1);
                }
            }
        }
    }
}

// ---------------- launch ----------------
extern "C" void kernel_launch(void* const* d_in, const int* in_sizes, int n_in,
                              void* d_out, int out_size) {
    const float* feats  = (const float*)d_in[0];
    const float* W1     = (const float*)d_in[1];
    const float* gamma1 = (const float*)d_in[2];
    const float* beta1  = (const float*)d_in[3];
    const float* W2     = (const float*)d_in[4];
    const float* gamma2 = (const float*)d_in[5];
    const float* beta2  = (const float*)d_in[6];
    const int*   nbr    = (const int*)d_in[7];
    const void*  mask   = (const void*)d_in[8];
    float*       out    = (float*)d_out;

    float* mid;
    cudaGetSymbolAddress((void**)&mid, g_mid);

    const int smem_bytes = (int)sizeof(Smem);
    cudaFuncSetAttribute(conv_mma<false>, cudaFuncAttributeMaxDynamicSharedMemorySize, smem_bytes);
    cudaFuncSetAttribute(conv_mma<true>,  cudaFuncAttributeMaxDynamicSharedMemorySize, smem_bytes);

    detect_mask_kernel<<<1, 256>>>((const unsigned int*)mask);
    build_nbr_kernel<<<(NPTS * KNBR + 255) / 256, 256>>>(nbr, mask);

    const int grid = (NPTS + BM - 1) / BM;  // 782
    conv_mma<false><<<grid, THREADS, smem_bytes>>>(feats, W1, gamma1, beta1, nullptr, mid);
    conv_mma<true><<<grid, THREADS, smem_bytes>>>(mid,  W2, gamma2, beta2, feats,   out);
}

// round 5
// speedup vs baseline: 3.9952x; 1.1230x over previous
#include <cuda_runtime.h>
#include <cstdint>
#include <math.h>

// ---------------- problem constants ----------------
#define NPTS 100000
#define KNBR 9
#define CDIM 256
#define BM   128                  // rows per CTA
#define THREADS 512               // 16 warps: 4 (M) x 4 (N)
#define KSTEP 32                  // channels per k-chunk
#define NKT  72                   // 9 neighbors * 256/32
#define NSTG 3                    // cp.async pipeline depth
#define RS   36                   // smem row stride (floats): 32 + 4 pad, 144B
#define A_STG_B (BM * RS * 4)     // 18432
#define B_STG_B (CDIM * RS * 4)   // 36864

// ---------------- scratch ----------------
__device__ int   g_mask_u8;
__device__ int   g_nbr[NPTS * KNBR];
__device__ float g_mid[(size_t)NPTS * CDIM];
__device__ float g_WT1[KNBR * CDIM * CDIM];   // [kk][d][c] (n-major)
__device__ float g_WT2[KNBR * CDIM * CDIM];

// ---------------- smem ----------------
struct Smem {
    float As[NSTG][BM][RS];       // m-major rows, 32 k + pad
    float Bs[NSTG][CDIM][RS];     // n-major rows, 32 k + pad
    int   nbr[BM * KNBR];
    float gam[CDIM], bet[CDIM];
    float red1[BM][4], red2[BM][4];
    float mu[BM], inv[BM];
};                                 // ~173.6 KB

// ---------------- helpers ----------------
__device__ __forceinline__ void cp16(uint32_t dst, const void* src, uint32_t sz) {
    asm volatile("cp.async.cg.shared.global [%0], [%1], 16, %2;"
                 :: "r"(dst), "l"(src), "r"(sz) : "memory");
}
#define CP_COMMIT() asm volatile("cp.async.commit_group;" ::: "memory")
#define CP_WAIT1()  asm volatile("cp.async.wait_group 1;" ::: "memory")

__device__ __forceinline__ void ldsm4(uint32_t* r, uint32_t addr) {
    asm volatile("ldmatrix.sync.aligned.m8n8.x4.shared.b16 {%0,%1,%2,%3}, [%4];"
                 : "=r"(r[0]), "=r"(r[1]), "=r"(r[2]), "=r"(r[3]) : "r"(addr));
}
__device__ __forceinline__ void mma8(float* c, const uint32_t* a, uint32_t b0, uint32_t b1) {
    asm volatile(
        "mma.sync.aligned.m16n8k8.row.col.f32.tf32.tf32.f32 "
        "{%0,%1,%2,%3}, {%4,%5,%6,%7}, {%8,%9}, {%0,%1,%2,%3};"
        : "+f"(c[0]), "+f"(c[1]), "+f"(c[2]), "+f"(c[3])
        : "r"(a[0]), "r"(a[1]), "r"(a[2]), "r"(a[3]), "r"(b0), "r"(b1));
}
__device__ __forceinline__ float gelu_exact(float x) {
    return 0.5f * x * (1.0f + erff(x * 0.70710678118654752f));
}

// ---------------- small kernels ----------------
__global__ void detect_mask_kernel(const unsigned int* __restrict__ m) {
    __shared__ int flag;
    if (threadIdx.x == 0) flag = 0;
    __syncthreads();
    for (int i = threadIdx.x; i < 1024; i += blockDim.x) {
        unsigned w = m[i];
        if (w != 0u && w != 1u && w != 0x3F800000u) flag = 1;
    }
    __syncthreads();
    if (threadIdx.x == 0) g_mask_u8 = flag;
}

__global__ void build_nbr_kernel(const int* __restrict__ idx, const void* __restrict__ mask) {
    int i = blockIdx.x * blockDim.x + threadIdx.x;
    if (i >= NPTS * KNBR) return;
    bool on = g_mask_u8 ? (((const unsigned char*)mask)[i] != 0)
                        : (((const unsigned int*)mask)[i] != 0u);
    g_nbr[i] = on ? idx[i] : -1;
}

// WT[kk][d][c] = W[kk][c][d]
__global__ void transpose_w(const float* __restrict__ W, float* __restrict__ WT) {
    __shared__ float t[32][33];
    int kk = blockIdx.z;
    int c0 = blockIdx.x * 32, d0 = blockIdx.y * 32;
    const float* Wk = W + (size_t)kk * 65536;
    float* Tk = WT + (size_t)kk * 65536;
    int x = threadIdx.x, y = threadIdx.y;
#pragma unroll
    for (int j = 0; j < 32; j += 8) t[y + j][x] = Wk[(c0 + y + j) * 256 + d0 + x];
    __syncthreads();
#pragma unroll
    for (int j = 0; j < 32; j += 8) Tk[(d0 + y + j) * 256 + c0 + x] = t[x][y + j];
}

// ---------------- stage loader (cp.async) ----------------
__device__ __forceinline__ void issue_stage(Smem* sm, int st, int kt,
                                            const float* __restrict__ src,
                                            const float* __restrict__ WT, int tid) {
    const int kk = kt >> 3;            // neighbor slot
    const int cb = (kt & 7) << 5;      // channel base
    // A gather: 128 rows x 32 floats, zero-fill if masked
    {
        const int row = tid >> 2, j = tid & 3;
        const int r = sm->nbr[row * KNBR + kk];
        const uint32_t sz = (r >= 0) ? 16u : 0u;
        const float* gp = src + ((size_t)(r >= 0 ? r : 0) << 8) + cb;
        cp16((uint32_t)__cvta_generic_to_shared(&sm->As[st][row][j * 4]),      gp + j * 4,      sz);
        cp16((uint32_t)__cvta_generic_to_shared(&sm->As[st][row][j * 4 + 16]), gp + j * 4 + 16, sz);
    }
    // B: 256 n-rows x 32 k floats from WT[kk][n][cb..cb+32)
    {
        const float* wb = WT + ((size_t)kk << 16) + cb;
#pragma unroll
        for (int q = 0; q < 4; q++) {
            const int c = q * THREADS + tid;
            const int n = c >> 3, kq = c & 7;
            cp16((uint32_t)__cvta_generic_to_shared(&sm->Bs[st][n][kq * 4]),
                 wb + ((size_t)n << 8) + kq * 4, 16u);
        }
    }
}

// ---------------- fused mma.sync conv + LN + GELU (+res) ----------------
template <bool HAS_RES>
__global__ __launch_bounds__(THREADS, 1)
void conv_mma(const float* __restrict__ src, const float* __restrict__ WT,
              const float* __restrict__ gamma, const float* __restrict__ beta,
              const float* __restrict__ resid, float* __restrict__ dst) {
    extern __shared__ unsigned char sm_raw[];
    Smem* sm = (Smem*)sm_raw;

    const int tid  = threadIdx.x;
    const int lane = tid & 31;
    const int wid  = tid >> 5;
    const int wm   = wid & 3;   // M warp coord (rows wm*32..+32)
    const int wn   = wid >> 2;  // N warp coord (cols wn*64..+64)
    const int m0   = blockIdx.x * BM;

    for (int i = tid; i < BM * KNBR; i += THREADS) {
        int m = m0 + i / KNBR;
        sm->nbr[i] = (m < NPTS) ? g_nbr[(size_t)m * KNBR + (i % KNBR)] : -1;
    }
    if (tid < CDIM) { sm->gam[tid] = gamma[tid]; sm->bet[tid] = beta[tid]; }
    __syncthreads();

    // ---- ldmatrix lane addresses (stage-0 base; add stage/ks offsets later) ----
    // A tiles: reg order a0..a3 = (rows 0-7,k 0-4),(rows 8-15,k 0-4),(0-7,k 4-8),(8-15,k 4-8)
    uint32_t aAddr[2];
    {
        const int rowsel = ((lane >> 3) & 1) * 8 + (lane & 7);
        const int kboff  = (lane >> 4) * 16;           // bytes
#pragma unroll
        for (int mt = 0; mt < 2; mt++) {
            const int arow = wm * 32 + mt * 16 + rowsel;
            aAddr[mt] = (uint32_t)__cvta_generic_to_shared(&sm->As[0][0][0])
                        + (uint32_t)(arow * (RS * 4) + kboff);
        }
    }
    // B tiles: reg order = b0(n0),b1(n0),b0(n0+8),b1(n0+8)
    uint32_t bAddr[4];
    {
        const int nrowsel = ((lane >> 4) & 1) * 8 + (lane & 7);
        const int kboff   = ((lane >> 3) & 1) * 16;    // bytes
#pragma unroll
        for (int p = 0; p < 4; p++) {
            const int brow = wn * 64 + p * 16 + nrowsel;
            bAddr[p] = (uint32_t)__cvta_generic_to_shared(&sm->Bs[0][0][0])
                       + (uint32_t)(brow * (RS * 4) + kboff);
        }
    }

    // prologue: stages 0,1
#pragma unroll
    for (int s = 0; s < NSTG - 1; s++) {
        issue_stage(sm, s, s, src, WT, tid);
        CP_COMMIT();
    }

    float acc[2][8][4];
#pragma unroll
    for (int mt = 0; mt < 2; mt++)
#pragma unroll
        for (int nt = 0; nt < 8; nt++)
#pragma unroll
            for (int e = 0; e < 4; e++) acc[mt][nt][e] = 0.0f;

    int cur = 0, nxt = NSTG - 1;   // stage indices (mod NSTG, no div)
    for (int kt = 0; kt < NKT; ++kt) {
        CP_WAIT1();
        __syncthreads();

        if (kt + NSTG - 1 < NKT)
            issue_stage(sm, nxt, kt + NSTG - 1, src, WT, tid);
        CP_COMMIT();

        const uint32_t ao = (uint32_t)cur * A_STG_B;
        const uint32_t bo = (uint32_t)cur * B_STG_B;
#pragma unroll
        for (int ks = 0; ks < 4; ks++) {
            uint32_t af0[4], af1[4];
            ldsm4(af0, aAddr[0] + ao + ks * 32);
            ldsm4(af1, aAddr[1] + ao + ks * 32);
#pragma unroll
            for (int p = 0; p < 4; p++) {
                uint32_t bf[4];
                ldsm4(bf, bAddr[p] + bo + ks * 32);
                mma8(acc[0][2 * p],     af0, bf[0], bf[1]);
                mma8(acc[1][2 * p],     af1, bf[0], bf[1]);
                mma8(acc[0][2 * p + 1], af0, bf[2], bf[3]);
                mma8(acc[1][2 * p + 1], af1, bf[2], bf[3]);
            }
        }
        cur = (cur + 1 == NSTG) ? 0 : cur + 1;
        nxt = (nxt + 1 == NSTG) ? 0 : nxt + 1;
    }

    // ---- LayerNorm reduction ----
    __syncthreads();
#pragma unroll
    for (int mt = 0; mt < 2; mt++) {
        float s1a = 0.f, s2a = 0.f, s1b = 0.f, s2b = 0.f;
#pragma unroll
        for (int nt = 0; nt < 8; nt++) {
            float v0 = acc[mt][nt][0], v1 = acc[mt][nt][1];
            float v2 = acc[mt][nt][2], v3 = acc[mt][nt][3];
            s1a += v0 + v1; s2a += v0 * v0 + v1 * v1;
            s1b += v2 + v3; s2b += v2 * v2 + v3 * v3;
        }
#pragma unroll
        for (int o = 1; o < 4; o <<= 1) {
            s1a += __shfl_xor_sync(0xFFFFFFFFu, s1a, o);
            s2a += __shfl_xor_sync(0xFFFFFFFFu, s2a, o);
            s1b += __shfl_xor_sync(0xFFFFFFFFu, s1b, o);
            s2b += __shfl_xor_sync(0xFFFFFFFFu, s2b, o);
        }
        if ((lane & 3) == 0) {
            int r = (wm << 5) + (mt << 4) + (lane >> 2);
            sm->red1[r][wn] = s1a; sm->red2[r][wn] = s2a;
            sm->red1[r + 8][wn] = s1b; sm->red2[r + 8][wn] = s2b;
        }
    }
    __syncthreads();
    if (tid < BM) {
        float s1 = sm->red1[tid][0] + sm->red1[tid][1] + sm->red1[tid][2] + sm->red1[tid][3];
        float s2 = sm->red2[tid][0] + sm->red2[tid][1] + sm->red2[tid][2] + sm->red2[tid][3];
        float mu  = s1 * (1.0f / 256.0f);
        float var = s2 * (1.0f / 256.0f) - mu * mu;
        sm->mu[tid]  = mu;
        sm->inv[tid] = rsqrtf(var + 1e-6f);
    }
    __syncthreads();

    // ---- normalize + residual + GELU + store ----
#pragma unroll
    for (int mt = 0; mt < 2; mt++) {
#pragma unroll
        for (int hf = 0; hf < 2; hf++) {
            int r = (wm << 5) + (mt << 4) + (lane >> 2) + hf * 8;
            int m = m0 + r;
            if (m < NPTS) {
                float mu = sm->mu[r], inv = sm->inv[r];
#pragma unroll
                for (int nt = 0; nt < 8; nt++) {
                    int n = (wn << 6) + nt * 8 + ((lane & 3) << 1);
                    float v0 = acc[mt][nt][hf * 2 + 0];
                    float v1 = acc[mt][nt][hf * 2 + 1];
                    v0 = (v0 - mu) * inv * sm->gam[n]     + sm->bet[n];
                    v1 = (v1 - mu) * inv * sm->gam[n + 1] + sm->bet[n + 1];
                    if (HAS_RES) {
                        float2 rr = *(const float2*)(resid + (size_t)m * CDIM + n);
                        v0 += rr.x; v1 += rr.y;
                    }
                    v0 = gelu_exact(v0);
                    v1 = gelu_exact(v1);
                    *(float2*)(dst + (size_t)m * CDIM + n) = make_float2(v0, v1);
                }
            }
        }
    }
}

// ---------------- launch ----------------
extern "C" void kernel_launch(void* const* d_in, const int* in_sizes, int n_in,
                              void* d_out, int out_size) {
    const float* feats  = (const float*)d_in[0];
    const float* W1     = (const float*)d_in[1];
    const float* gamma1 = (const float*)d_in[2];
    const float* beta1  = (const float*)d_in[3];
    const float* W2     = (const float*)d_in[4];
    const float* gamma2 = (const float*)d_in[5];
    const float* beta2  = (const float*)d_in[6];
    const int*   nbr    = (const int*)d_in[7];
    const void*  mask   = (const void*)d_in[8];
    float*       out    = (float*)d_out;

    float *mid, *wt1, *wt2;
    cudaGetSymbolAddress((void**)&mid, g_mid);
    cudaGetSymbolAddress((void**)&wt1, g_WT1);
    cudaGetSymbolAddress((void**)&wt2, g_WT2);

    const int smem_bytes = (int)sizeof(Smem);
    cudaFuncSetAttribute(conv_mma<false>, cudaFuncAttributeMaxDynamicSharedMemorySize, smem_bytes);
    cudaFuncSetAttribute(conv_mma<true>,  cudaFuncAttributeMaxDynamicSharedMemorySize, smem_bytes);

    detect_mask_kernel<<<1, 256>>>((const unsigned int*)mask);
    build_nbr_kernel<<<(NPTS * KNBR + 255) / 256, 256>>>(nbr, mask);

    dim3 tb(32, 8), tg(8, 8, KNBR);
    transpose_w<<<tg, tb>>>(W1, wt1);
    transpose_w<<<tg, tb>>>(W2, wt2);

    const int grid = (NPTS + BM - 1) / BM;  // 782
    conv_mma<false><<<grid, THREADS, smem_bytes>>>(feats, wt1, gamma1, beta1, nullptr, mid);
    conv_mma<true><<<grid, THREADS, smem_bytes>>>(mid,  wt2, gamma2, beta2, feats,   out);
}

// round 6
// speedup vs baseline: 6.6115x; 1.6549x over previous
#include <cuda_runtime.h>
#include <cuda_fp16.h>
#include <cstdint>
#include <math.h>

// ---------------- problem constants ----------------
#define NPTS 100000
#define KNBR 9
#define CDIM 256
#define BM   128                  // rows per CTA
#define THREADS 512               // 16 warps: 4 (M) x 4 (N)
#define KSTEP 64                  // channels per k-chunk (fp16)
#define NKT  36                   // 9 neighbors * 256/64
#define NSTG 3                    // cp.async pipeline depth
#define RS   72                   // smem row stride in halves (64 + 8 pad = 144B)
#define A_STG_B (BM * RS * 2)     // 18432
#define B_STG_B (CDIM * RS * 2)   // 36864

// ---------------- scratch ----------------
__device__ int    g_mask_u8;
__device__ int    g_nbr[NPTS * KNBR];
__device__ __half g_hfeats[(size_t)NPTS * CDIM];
__device__ __half g_mid[(size_t)NPTS * CDIM];
__device__ __half g_WT1[KNBR * CDIM * CDIM];   // [kk][d][c] (n-major), fp16
__device__ __half g_WT2[KNBR * CDIM * CDIM];

// ---------------- smem ----------------
struct Smem {
    __half As[NSTG][BM][RS];      // m-major rows, 64 k + pad      55296 B
    __half Bs[NSTG][CDIM][RS];    // n-major rows, 64 k + pad     110592 B
    int    nbr[BM * KNBR];
    float  gam[CDIM], bet[CDIM];
    float  red1[BM][4], red2[BM][4];
    float  mu[BM], inv[BM];
};                                 // ~176 KB

// ---------------- helpers ----------------
__device__ __forceinline__ void cp16(uint32_t dst, const void* src, uint32_t sz) {
    asm volatile("cp.async.cg.shared.global [%0], [%1], 16, %2;"
                 :: "r"(dst), "l"(src), "r"(sz) : "memory");
}
#define CP_COMMIT() asm volatile("cp.async.commit_group;" ::: "memory")
#define CP_WAIT1()  asm volatile("cp.async.wait_group 1;" ::: "memory")

__device__ __forceinline__ void ldsm4(uint32_t* r, uint32_t addr) {
    asm volatile("ldmatrix.sync.aligned.m8n8.x4.shared.b16 {%0,%1,%2,%3}, [%4];"
                 : "=r"(r[0]), "=r"(r[1]), "=r"(r[2]), "=r"(r[3]) : "r"(addr));
}
__device__ __forceinline__ void mma16(float* c, const uint32_t* a, uint32_t b0, uint32_t b1) {
    asm volatile(
        "mma.sync.aligned.m16n8k16.row.col.f32.f16.f16.f32 "
        "{%0,%1,%2,%3}, {%4,%5,%6,%7}, {%8,%9}, {%0,%1,%2,%3};"
        : "+f"(c[0]), "+f"(c[1]), "+f"(c[2]), "+f"(c[3])
        : "r"(a[0]), "r"(a[1]), "r"(a[2]), "r"(a[3]), "r"(b0), "r"(b1));
}
__device__ __forceinline__ float gelu_exact(float x) {
    return 0.5f * x * (1.0f + erff(x * 0.70710678118654752f));
}

// ---------------- small kernels ----------------
__global__ void detect_mask_kernel(const unsigned int* __restrict__ m) {
    __shared__ int flag;
    if (threadIdx.x == 0) flag = 0;
    __syncthreads();
    for (int i = threadIdx.x; i < 1024; i += blockDim.x) {
        unsigned w = m[i];
        if (w != 0u && w != 1u && w != 0x3F800000u) flag = 1;
    }
    __syncthreads();
    if (threadIdx.x == 0) g_mask_u8 = flag;
}

__global__ void build_nbr_kernel(const int* __restrict__ idx, const void* __restrict__ mask) {
    int i = blockIdx.x * blockDim.x + threadIdx.x;
    if (i >= NPTS * KNBR) return;
    bool on = g_mask_u8 ? (((const unsigned char*)mask)[i] != 0)
                        : (((const unsigned int*)mask)[i] != 0u);
    g_nbr[i] = on ? idx[i] : -1;
}

// feats f32 -> f16
__global__ void f2h_kernel(const float* __restrict__ in, __half* __restrict__ out) {
    const int n4 = NPTS * CDIM / 4;
    for (int i = blockIdx.x * blockDim.x + threadIdx.x; i < n4; i += gridDim.x * blockDim.x) {
        float4 v = __ldg((const float4*)in + i);
        __half2 h0 = __floats2half2_rn(v.x, v.y);
        __half2 h1 = __floats2half2_rn(v.z, v.w);
        ((uint2*)out)[i] = make_uint2(*(uint32_t*)&h0, *(uint32_t*)&h1);
    }
}

// WT[kk][d][c] = (half)W[kk][c][d]
__global__ void transpose_w(const float* __restrict__ W, __half* __restrict__ WT) {
    __shared__ float t[32][33];
    int kk = blockIdx.z;
    int c0 = blockIdx.x * 32, d0 = blockIdx.y * 32;
    const float* Wk = W + (size_t)kk * 65536;
    __half* Tk = WT + (size_t)kk * 65536;
    int x = threadIdx.x, y = threadIdx.y;
#pragma unroll
    for (int j = 0; j < 32; j += 8) t[y + j][x] = Wk[(c0 + y + j) * 256 + d0 + x];
    __syncthreads();
#pragma unroll
    for (int j = 0; j < 32; j += 8) Tk[(d0 + y + j) * 256 + c0 + x] = __float2half(t[x][y + j]);
}

// ---------------- stage loader (cp.async, fp16) ----------------
__device__ __forceinline__ void issue_stage(Smem* sm, int st, int kt,
                                            const __half* __restrict__ src,
                                            const __half* __restrict__ WT, int tid) {
    const int kk = kt >> 2;            // neighbor slot
    const int cb = (kt & 3) << 6;      // channel base (halves)
    // A gather: 128 rows x 64 halves (128B/row), zero-fill if masked
    {
        const int row = tid >> 2, j = tid & 3;
        const int r = sm->nbr[row * KNBR + kk];
        const uint32_t sz = (r >= 0) ? 16u : 0u;
        const __half* gp = src + ((size_t)(r >= 0 ? r : 0) << 8) + cb;
        cp16((uint32_t)__cvta_generic_to_shared(&sm->As[st][row][j * 8]),      gp + j * 8,      sz);
        cp16((uint32_t)__cvta_generic_to_shared(&sm->As[st][row][j * 8 + 32]), gp + j * 8 + 32, sz);
    }
    // B: 256 n-rows x 64 halves from WT[kk][n][cb..cb+64)
    {
        const __half* wb = WT + ((size_t)kk << 16) + cb;
#pragma unroll
        for (int q = 0; q < 4; q++) {
            const int c = q * THREADS + tid;
            const int n = c >> 3, kq = c & 7;
            cp16((uint32_t)__cvta_generic_to_shared(&sm->Bs[st][n][kq * 8]),
                 wb + ((size_t)n << 8) + kq * 8, 16u);
        }
    }
}

// ---------------- fused fp16 mma conv + LN + GELU (+res) ----------------
template <bool HAS_RES, bool HALF_OUT>
__global__ __launch_bounds__(THREADS, 1)
void conv_mma(const __half* __restrict__ src, const __half* __restrict__ WT,
              const float* __restrict__ gamma, const float* __restrict__ beta,
              const float* __restrict__ resid, void* __restrict__ dst_v) {
    extern __shared__ unsigned char sm_raw[];
    Smem* sm = (Smem*)sm_raw;

    const int tid  = threadIdx.x;
    const int lane = tid & 31;
    const int wid  = tid >> 5;
    const int wm   = wid & 3;   // M warp coord
    const int wn   = wid >> 2;  // N warp coord
    const int m0   = blockIdx.x * BM;

    for (int i = tid; i < BM * KNBR; i += THREADS) {
        int m = m0 + i / KNBR;
        sm->nbr[i] = (m < NPTS) ? g_nbr[(size_t)m * KNBR + (i % KNBR)] : -1;
    }
    if (tid < CDIM) { sm->gam[tid] = gamma[tid]; sm->bet[tid] = beta[tid]; }
    __syncthreads();

    // ---- ldmatrix lane addresses ----
    // A (16x16 f16): T0=(r0-7,k0-7) T1=(r8-15,k0-7) T2=(r0-7,k8-15) T3=(r8-15,k8-15)
    uint32_t aAddr[2];
    {
        const int rowsel = ((lane >> 3) & 1) * 8 + (lane & 7);
        const int kboff  = (lane >> 4) * 16;           // 8 halves = 16B
#pragma unroll
        for (int mt = 0; mt < 2; mt++) {
            const int arow = wm * 32 + mt * 16 + rowsel;
            aAddr[mt] = (uint32_t)__cvta_generic_to_shared(&sm->As[0][0][0])
                        + (uint32_t)(arow * (RS * 2) + kboff);
        }
    }
    // B n-major (two n8 groups x k16): T0=(n0-7,klo) T1=(n0-7,khi) T2=(n8-15,klo) T3=(n8-15,khi)
    uint32_t bAddr[4];
    {
        const int nrowsel = ((lane >> 4) & 1) * 8 + (lane & 7);
        const int kboff   = ((lane >> 3) & 1) * 16;
#pragma unroll
        for (int p = 0; p < 4; p++) {
            const int brow = wn * 64 + p * 16 + nrowsel;
            bAddr[p] = (uint32_t)__cvta_generic_to_shared(&sm->Bs[0][0][0])
                       + (uint32_t)(brow * (RS * 2) + kboff);
        }
    }

    // prologue
#pragma unroll
    for (int s = 0; s < NSTG - 1; s++) {
        issue_stage(sm, s, s, src, WT, tid);
        CP_COMMIT();
    }

    float acc[2][8][4];
#pragma unroll
    for (int mt = 0; mt < 2; mt++)
#pragma unroll
        for (int nt = 0; nt < 8; nt++)
#pragma unroll
            for (int e = 0; e < 4; e++) acc[mt][nt][e] = 0.0f;

    int cur = 0, nxt = NSTG - 1;
    for (int kt = 0; kt < NKT; ++kt) {
        CP_WAIT1();
        __syncthreads();

        if (kt + NSTG - 1 < NKT)
            issue_stage(sm, nxt, kt + NSTG - 1, src, WT, tid);
        CP_COMMIT();

        const uint32_t ao = (uint32_t)cur * A_STG_B;
        const uint32_t bo = (uint32_t)cur * B_STG_B;
#pragma unroll
        for (int ks = 0; ks < 4; ks++) {           // 4 k-steps of 16
            uint32_t af0[4], af1[4];
            ldsm4(af0, aAddr[0] + ao + ks * 32);   // 16 halves = 32B per step
            ldsm4(af1, aAddr[1] + ao + ks * 32);
#pragma unroll
            for (int p = 0; p < 4; p++) {
                uint32_t bf[4];
                ldsm4(bf, bAddr[p] + bo + ks * 32);
                mma16(acc[0][2 * p],     af0, bf[0], bf[1]);
                mma16(acc[1][2 * p],     af1, bf[0], bf[1]);
                mma16(acc[0][2 * p + 1], af0, bf[2], bf[3]);
                mma16(acc[1][2 * p + 1], af1, bf[2], bf[3]);
            }
        }
        cur = (cur + 1 == NSTG) ? 0 : cur + 1;
        nxt = (nxt + 1 == NSTG) ? 0 : nxt + 1;
    }

    // ---- LayerNorm reduction ----
    __syncthreads();
#pragma unroll
    for (int mt = 0; mt < 2; mt++) {
        float s1a = 0.f, s2a = 0.f, s1b = 0.f, s2b = 0.f;
#pragma unroll
        for (int nt = 0; nt < 8; nt++) {
            float v0 = acc[mt][nt][0], v1 = acc[mt][nt][1];
            float v2 = acc[mt][nt][2], v3 = acc[mt][nt][3];
            s1a += v0 + v1; s2a += v0 * v0 + v1 * v1;
            s1b += v2 + v3; s2b += v2 * v2 + v3 * v3;
        }
#pragma unroll
        for (int o = 1; o < 4; o <<= 1) {
            s1a += __shfl_xor_sync(0xFFFFFFFFu, s1a, o);
            s2a += __shfl_xor_sync(0xFFFFFFFFu, s2a, o);
            s1b += __shfl_xor_sync(0xFFFFFFFFu, s1b, o);
            s2b += __shfl_xor_sync(0xFFFFFFFFu, s2b, o);
        }
        if ((lane & 3) == 0) {
            int r = (wm << 5) + (mt << 4) + (lane >> 2);
            sm->red1[r][wn] = s1a; sm->red2[r][wn] = s2a;
            sm->red1[r + 8][wn] = s1b; sm->red2[r + 8][wn] = s2b;
        }
    }
    __syncthreads();
    if (tid < BM) {
        float s1 = sm->red1[tid][0] + sm->red1[tid][1] + sm->red1[tid][2] + sm->red1[tid][3];
        float s2 = sm->red2[tid][0] + sm->red2[tid][1] + sm->red2[tid][2] + sm->red2[tid][3];
        float mu  = s1 * (1.0f / 256.0f);
        float var = s2 * (1.0f / 256.0f) - mu * mu;
        sm->mu[tid]  = mu;
        sm->inv[tid] = rsqrtf(var + 1e-6f);
    }
    __syncthreads();

    // ---- normalize + residual + GELU + store ----
#pragma unroll
    for (int mt = 0; mt < 2; mt++) {
#pragma unroll
        for (int hf = 0; hf < 2; hf++) {
            int r = (wm << 5) + (mt << 4) + (lane >> 2) + hf * 8;
            int m = m0 + r;
            if (m < NPTS) {
                float mu = sm->mu[r], inv = sm->inv[r];
#pragma unroll
                for (int nt = 0; nt < 8; nt++) {
                    int n = (wn << 6) + nt * 8 + ((lane & 3) << 1);
                    float v0 = acc[mt][nt][hf * 2 + 0];
                    float v1 = acc[mt][nt][hf * 2 + 1];
                    v0 = (v0 - mu) * inv * sm->gam[n]     + sm->bet[n];
                    v1 = (v1 - mu) * inv * sm->gam[n + 1] + sm->bet[n + 1];
                    if (HAS_RES) {
                        float2 rr = *(const float2*)(resid + (size_t)m * CDIM + n);
                        v0 += rr.x; v1 += rr.y;
                    }
                    v0 = gelu_exact(v0);
                    v1 = gelu_exact(v1);
                    if (HALF_OUT) {
                        __half2 h = __floats2half2_rn(v0, v1);
                        *(__half2*)((__half*)dst_v + (size_t)m * CDIM + n) = h;
                    } else {
                        *(float2*)((float*)dst_v + (size_t)m * CDIM + n) = make_float2(v0, v1);
                    }
                }
            }
        }
    }
}

// ---------------- launch ----------------
extern "C" void kernel_launch(void* const* d_in, const int* in_sizes, int n_in,
                              void* d_out, int out_size) {
    const float* feats  = (const float*)d_in[0];
    const float* W1     = (const float*)d_in[1];
    const float* gamma1 = (const float*)d_in[2];
    const float* beta1  = (const float*)d_in[3];
    const float* W2     = (const float*)d_in[4];
    const float* gamma2 = (const float*)d_in[5];
    const float* beta2  = (const float*)d_in[6];
    const int*   nbr    = (const int*)d_in[7];
    const void*  mask   = (const void*)d_in[8];

    __half *hfeats, *mid, *wt1, *wt2;
    cudaGetSymbolAddress((void**)&hfeats, g_hfeats);
    cudaGetSymbolAddress((void**)&mid, g_mid);
    cudaGetSymbolAddress((void**)&wt1, g_WT1);
    cudaGetSymbolAddress((void**)&wt2, g_WT2);

    const int smem_bytes = (int)sizeof(Smem);
    cudaFuncSetAttribute(conv_mma<false, true>, cudaFuncAttributeMaxDynamicSharedMemorySize, smem_bytes);
    cudaFuncSetAttribute(conv_mma<true, false>, cudaFuncAttributeMaxDynamicSharedMemorySize, smem_bytes);

    detect_mask_kernel<<<1, 256>>>((const unsigned int*)mask);
    build_nbr_kernel<<<(NPTS * KNBR + 255) / 256, 256>>>(nbr, mask);
    f2h_kernel<<<512, 256>>>(feats, hfeats);

    dim3 tb(32, 8), tg(8, 8, KNBR);
    transpose_w<<<tg, tb>>>(W1, wt1);
    transpose_w<<<tg, tb>>>(W2, wt2);

    const int grid = (NPTS + BM - 1) / BM;  // 782
    conv_mma<false, true><<<grid, THREADS, smem_bytes>>>(hfeats, wt1, gamma1, beta1, nullptr, mid);
    conv_mma<true, false><<<grid, THREADS, smem_bytes>>>(mid,  wt2, gamma2, beta2, feats, d_out);
}